// round 10
// baseline (speedup 1.0000x reference)
#include <cuda_runtime.h>

// ---------------- problem constants ----------------
#define KB     8
#define KC     64
#define KHW    76800      // 240*320
#define KCL    10
#define ALPHA_C   0.02f
#define DELTA_C   0.5f
#define MINW_C    50.0f

// pass-1 tiling: (b, chunk, cgrp) -> 960 blocks of 1280 pixels, 32 channels
#define CHUNKS1 60
#define PX1     (KHW / CHUNKS1)     // 1280
#define NBLK1   (KB * CHUNKS1 * 2)  // 960

// pass-2 tiling: 1200 blocks of 512 pixels (128 thr * 4 px)
#define CHUNKS3 150
#define PX3     (KHW / CHUNKS3)     // 512
#define NBLK3   (KB * CHUNKS3)      // 1200

// ---------------- device scratch (zero-init .bss; launches restore) -------
__device__ float g_sums[KB][KC][KCL];     // K1 accumulates; K1-finalize zeroes
__device__ float g_cnt[KB][KCL];          // K1 accumulates; K1-finalize zeroes
__device__ float g_means[KB][KCL][KC];    // K1-finalize overwrites
__device__ float g_inter;                 // K1-finalize overwrites
__device__ float g_d2[KB * KCL];          // K3 accumulates; K3-finalize zeroes
__device__ float g_nk[KB * KCL];          // K3 accumulates; K3-finalize zeroes
__device__ unsigned int g_tick1;          // K1 ticket; finalize zeroes
__device__ unsigned int g_tick3;          // K3 ticket; finalize zeroes

// empty kernel: shifts ncu capture index so -s 5 -c 1 lands on k1_sums
__global__ void k_nop() {}

// =====================================================================
// K1: per-cluster channel sums + counts via warp-private smem bins.
// 8 warps/block; warp owns 4 channels; lane owns a pixel quad.
// Software-pipelined: LDG burst for it+1 issues BEFORE scatter of it.
// Scatter uses float2 bins (LDS.64/STS.64, conflict-free: 16-lane
// phases each cover banks 0..31) -> half the smem instructions.
// Fused finalize: normalized means + inter hinge loss.
// =====================================================================
__global__ __launch_bounds__(256, 4) void k1_sums(const float* __restrict__ x,
                                                  const int* __restrict__ cmask)
{
    __shared__ unsigned char s_cm[PX1];
    __shared__ int s_cnt[KCL];
    __shared__ float2 s_acc2[8][KCL * 2 * 32];   // 8 warps x 640 float2 = 40 KB
    __shared__ unsigned int s_last;
    __shared__ float s_r[8];

    const int bid   = blockIdx.x;
    const int b     = bid / (CHUNKS1 * 2);
    const int r0    = bid % (CHUNKS1 * 2);
    const int cgrp  = r0 & 1;
    const int pbase = (r0 >> 1) * PX1;
    const int tid   = threadIdx.x;
    const int lane  = tid & 31;
    const int warp  = tid >> 5;

    if (tid < KCL) s_cnt[tid] = 0;

    // zero this warp's bins (warp-private: no cross-warp sync needed)
    float2* wacc2 = s_acc2[warp];
#pragma unroll
    for (int i = 0; i < (KCL * 2 * 32) / 32; i++)
        wacc2[i * 32 + lane] = make_float2(0.f, 0.f);

    // stage masks (+ counts only from channel-group 0)
    const int* cmb = cmask + b * KHW + pbase;
    if (cgrp == 0) {
        int cnt[KCL];
#pragma unroll
        for (int k = 0; k < KCL; k++) cnt[k] = 0;
#pragma unroll
        for (int i = 0; i < PX1 / 256; i++) {
            const int p = tid + i * 256;
            const int v = cmb[p];
            s_cm[p] = (unsigned char)v;
#pragma unroll
            for (int k = 0; k < KCL; k++) cnt[k] += (v == k);
        }
        __syncthreads();
#pragma unroll
        for (int k = 0; k < KCL; k++) {
            int v = cnt[k];
#pragma unroll
            for (int o = 16; o; o >>= 1) v += __shfl_xor_sync(0xffffffffu, v, o);
            if (lane == 0) atomicAdd(&s_cnt[k], v);
        }
        __syncthreads();
        if (tid < KCL) atomicAdd(&g_cnt[b][tid], (float)s_cnt[tid]);
    } else {
#pragma unroll
        for (int i = 0; i < PX1 / 256; i++) {
            const int p = tid + i * 256;
            s_cm[p] = (unsigned char)cmb[p];
        }
        __syncthreads();
    }

    // ---- main accumulation: software-pipelined quad loop ----
    const int c0 = cgrp * 32 + warp * 4;
    const float* xp = x + ((size_t)(b * KC + c0)) * KHW + pbase;

#define LOADQ(d0, d1, d2, d3, P)                                   \
    d0 = *(const float4*)(xp + (P));                               \
    d1 = *(const float4*)(xp + (size_t)KHW + (P));                 \
    d2 = *(const float4*)(xp + (size_t)2 * KHW + (P));             \
    d3 = *(const float4*)(xp + (size_t)3 * KHW + (P))

#define SCATTER_PX(KV, V0, V1, V2, V3) do {                        \
    float2* a = wacc2 + (KV) * 64 + lane;                          \
    float2 t0 = a[0];  t0.x += (V0); t0.y += (V1); a[0]  = t0;     \
    float2 t1 = a[32]; t1.x += (V2); t1.y += (V3); a[32] = t1;     \
} while (0)

    float4 c0v, c1v, c2v, c3v;
    unsigned int cmq;
    {
        const int p = 4 * lane;
        LOADQ(c0v, c1v, c2v, c3v, p);
        cmq = *(const unsigned int*)(s_cm + p);
    }

#pragma unroll
    for (int it = 0; it < PX1 / 128; it++) {
        float4 n0, n1, n2, n3;
        unsigned int cmn = 0;
        if (it + 1 < PX1 / 128) {
            const int pn = 4 * lane + (it + 1) * 128;
            LOADQ(n0, n1, n2, n3, pn);                 // burst for it+1
            cmn = *(const unsigned int*)(s_cm + pn);
        }

        // scatter current quad (overlaps with the burst above)
        SCATTER_PX(cmq & 0xffu,         c0v.x, c1v.x, c2v.x, c3v.x);
        SCATTER_PX((cmq >> 8) & 0xffu,  c0v.y, c1v.y, c2v.y, c3v.y);
        SCATTER_PX((cmq >> 16) & 0xffu, c0v.z, c1v.z, c2v.z, c3v.z);
        SCATTER_PX(cmq >> 24,           c0v.w, c1v.w, c2v.w, c3v.w);

        c0v = n0; c1v = n1; c2v = n2; c3v = n3; cmq = cmn;
    }
#undef LOADQ
#undef SCATTER_PX

    // ---- per-warp reduce of bins -> global atomics ----
    // row r = k*2 + jp; holds channels (c0+2jp, c0+2jp+1) for cluster k
#pragma unroll
    for (int r = 0; r < KCL * 2; r++) {
        float2 v = wacc2[r * 32 + lane];
#pragma unroll
        for (int o = 16; o; o >>= 1) {
            v.x += __shfl_xor_sync(0xffffffffu, v.x, o);
            v.y += __shfl_xor_sync(0xffffffffu, v.y, o);
        }
        if (lane == 0) {
            const int k  = r >> 1;
            const int jp = r & 1;
            atomicAdd(&g_sums[b][c0 + 2 * jp][k],     v.x);
            atomicAdd(&g_sums[b][c0 + 2 * jp + 1][k], v.y);
        }
    }

    // ---- ticket: last block computes means + inter loss ----
    __threadfence();
    __syncthreads();
    if (tid == 0)
        s_last = (atomicAdd(&g_tick1, 1u) == (unsigned)(NBLK1 - 1)) ? 1u : 0u;
    __syncthreads();
    if (!s_last) return;
    __threadfence();

    // bins are dead now; alias them as the means staging buffer (80x65 floats)
    float* s_means = (float*)&s_acc2[0][0];

    // means: 80 rows (b,k); warp per row stripe, lanes cover c and c+32
    for (int row = warp; row < KB * KCL; row += 8) {
        const int bb = row / KCL;
        const int kk = row % KCL;
        const float cntv = g_cnt[bb][kk];
        const float m0 = g_sums[bb][lane][kk]      / (cntv + 1e-10f);
        const float m1 = g_sums[bb][lane + 32][kk] / (cntv + 1e-10f);
        float sq = m0 * m0 + m1 * m1;
#pragma unroll
        for (int o = 16; o; o >>= 1) sq += __shfl_xor_sync(0xffffffffu, sq, o);
        const float inv = 1.0f / fmaxf(sqrtf(sq), 1e-12f);
        const float n0 = m0 * inv, n1 = m1 * inv;
        g_means[bb][kk][lane]      = n0;
        g_means[bb][kk][lane + 32] = n1;
        s_means[row * 65 + lane]      = n0;
        s_means[row * 65 + lane + 32] = n1;
        // reset for next launch
        g_sums[bb][lane][kk]      = 0.0f;
        g_sums[bb][lane + 32][kk] = 0.0f;
        if (lane == 0) g_cnt[bb][kk] = 0.0f;
    }
    __syncthreads();

    // inter loss: warp-per-ordered-pair (720 pairs / 8 warps), lane0 accum
    float acc_inter = 0.f;
    for (int pr = warp; pr < KB * KCL * (KCL - 1); pr += 8) {
        const int bb = pr / 90;
        const int r  = pr % 90;
        const int k  = r / 9;
        int l = r % 9; if (l >= k) l++;
        const float* mk = &s_means[(bb * KCL + k) * 65];
        const float* ml = &s_means[(bb * KCL + l) * 65];
        float dv = mk[lane] * ml[lane] + mk[lane + 32] * ml[lane + 32];
#pragma unroll
        for (int o = 16; o; o >>= 1) dv += __shfl_xor_sync(0xffffffffu, dv, o);
        const float h = fmaxf(DELTA_C - 0.5f * (1.0f - dv), 0.0f);
        if (lane == 0) acc_inter += h * h;
    }
    if (lane == 0) s_r[warp] = acc_inter;
    __syncthreads();
    if (tid == 0) {
        float t = 0.f;
#pragma unroll
        for (int w = 0; w < 8; w++) t += s_r[w];
        g_inter = t;
        g_tick1 = 0u;
    }
}

// =====================================================================
// K3: second pass, 4 px/thread, channels in 8-wide windows with an
// explicit 8x LDG.128 load burst. Small smem (~3 KB).
// Ticket-last-block finalize: intra + combine with g_inter.
// =====================================================================
__global__ __launch_bounds__(128, 8) void k3_intra(const float* __restrict__ x,
                                                   const int* __restrict__ cmask,
                                                   float* __restrict__ out)
{
    __shared__ float msh[KCL * 65];
    __shared__ float s_d2[KCL];
    __shared__ float s_nk[KCL];
    __shared__ unsigned int s_last;

    const int bid   = blockIdx.x;
    const int b     = bid / CHUNKS3;
    const int pbase = (bid % CHUNKS3) * PX3;
    const int tid   = threadIdx.x;
    const int lane  = tid & 31;
    const int warp  = tid >> 5;

#pragma unroll
    for (int i = 0; i < 5; i++) {
        const int idx = tid + i * 128;
        msh[(idx >> 6) * 65 + (idx & 63)] = ((const float*)g_means)[b * KCL * KC + idx];
    }
    if (tid < KCL) { s_d2[tid] = 0.f; s_nk[tid] = 0.f; }
    __syncthreads();

    const int p0 = pbase + tid * 4;
    const int4 cm4 = *(const int4*)(cmask + b * KHW + p0);
    const float* xb = x + (size_t)b * KC * KHW + p0;

    const int kk4[4] = { cm4.x, cm4.y, cm4.z, cm4.w };
    const float* mp0 = &msh[cm4.x * 65];
    const float* mp1 = &msh[cm4.y * 65];
    const float* mp2 = &msh[cm4.z * 65];
    const float* mp3 = &msh[cm4.w * 65];

    float d0 = 0.f, d1 = 0.f, d2 = 0.f, d3 = 0.f;

#pragma unroll
    for (int w = 0; w < KC / 8; w++) {
        // ---- load burst: 8 channels in flight ----
        float4 buf[8];
#pragma unroll
        for (int cc = 0; cc < 8; cc++)
            buf[cc] = *(const float4*)(xb + (size_t)(w * 8 + cc) * KHW);
        // ---- compute phase ----
#pragma unroll
        for (int cc = 0; cc < 8; cc++) {
            const int c = w * 8 + cc;
            d0 = fmaf(buf[cc].x, mp0[c], d0);
            d1 = fmaf(buf[cc].y, mp1[c], d1);
            d2 = fmaf(buf[cc].z, mp2[c], d2);
            d3 = fmaf(buf[cc].w, mp3[c], d3);
        }
    }

    const float dots[4] = { d0, d1, d2, d3 };
#pragma unroll
    for (int i = 0; i < 4; i++) {
        const float dd = 0.5f * (1.0f - dots[i]);
        atomicAdd(&s_d2[kk4[i]], dd * dd);
        if (dd > ALPHA_C) atomicAdd(&s_nk[kk4[i]], 1.0f);
    }
    __syncthreads();
    if (tid < KCL) {
        atomicAdd(&g_d2[b * KCL + tid], s_d2[tid]);
        atomicAdd(&g_nk[b * KCL + tid], s_nk[tid]);
    }

    // ---- ticket: last block finalizes ----
    __threadfence();
    __syncthreads();
    if (tid == 0)
        s_last = (atomicAdd(&g_tick3, 1u) == (unsigned)(NBLK3 - 1)) ? 1u : 0u;
    __syncthreads();
    if (!s_last) return;
    __threadfence();

    // intra finalize + resets (80 values)
    float acc_intra = 0.f, acc_ind = 0.f;
    if (tid < KB * KCL) {
        const float nk = g_nk[tid];
        acc_intra = g_d2[tid] / (fmaxf(nk, MINW_C) * (float)KCL);
        acc_ind   = nk;
        g_nk[tid] = 0.f;
        g_d2[tid] = 0.f;
    }

    float v1 = acc_intra, v2 = acc_ind;
#pragma unroll
    for (int o = 16; o; o >>= 1) {
        v1 += __shfl_xor_sync(0xffffffffu, v1, o);
        v2 += __shfl_xor_sync(0xffffffffu, v2, o);
    }
    __shared__ float s_r1[4], s_r2[4];
    if (lane == 0) { s_r1[warp] = v1; s_r2[warp] = v2; }
    __syncthreads();
    if (tid == 0) {
        float t1 = 0.f, t2 = 0.f;
#pragma unroll
        for (int w = 0; w < 4; w++) { t1 += s_r1[w]; t2 += s_r2[w]; }
        const float inter_loss = g_inter / ((float)(KCL * (KCL - 1) / 2) * (float)KB);
        const float intra_loss = (t2 > 0.f) ? (t1 / (float)KB) : 0.f;
        out[0] = intra_loss + inter_loss;
        out[1] = intra_loss;
        out[2] = inter_loss;
        g_tick3 = 0u;
    }
}

// =====================================================================
// Launch order [nop, k1, k3, nop]: ncu's -s 5 -c 1 capture (launch
// index 5) lands on the 2nd call's k1_sums, finally profiling pass 1.
// =====================================================================
extern "C" void kernel_launch(void* const* d_in, const int* in_sizes, int n_in,
                              void* d_out, int out_size)
{
    const float* x   = (const float*)d_in[0];
    const int*   cm  = (const int*)d_in[1];
    float*       out = (float*)d_out;

    k_nop<<<1, 1>>>();
    k1_sums<<<NBLK1, 256>>>(x, cm);
    k3_intra<<<NBLK3, 128>>>(x, cm, out);
    k_nop<<<1, 1>>>();
}

// round 11
// speedup vs baseline: 1.0624x; 1.0624x over previous
#include <cuda_runtime.h>

// ---------------- problem constants ----------------
#define KB     8
#define KC     64
#define KHW    76800      // 240*320
#define KCL    10
#define ALPHA_C   0.02f
#define DELTA_C   0.5f
#define MINW_C    50.0f

// pass-1 tiling: (b, chunk, cgrp) -> 960 blocks of 1280 pixels, 32 channels
#define CHUNKS1 60
#define PX1     (KHW / CHUNKS1)     // 1280
#define NBLK1   (KB * CHUNKS1 * 2)  // 960

// pass-2 tiling: 1200 blocks of 512 pixels (128 thr * 4 px)
#define CHUNKS3 150
#define PX3     (KHW / CHUNKS3)     // 512
#define NBLK3   (KB * CHUNKS3)      // 1200

// ---------------- device scratch (zero-init .bss; launches restore) -------
__device__ float g_sums[KB][KC][KCL];     // K1 accumulates; K1-finalize zeroes
__device__ float g_cnt[KB][KCL];          // K1 accumulates; K1-finalize zeroes
__device__ float g_means[KB][KCL][KC];    // K1-finalize overwrites
__device__ float g_inter;                 // K1-finalize overwrites
__device__ float g_d2[KB * KCL];          // K3 accumulates; K3-finalize zeroes
__device__ float g_nk[KB * KCL];          // K3 accumulates; K3-finalize zeroes
__device__ unsigned int g_tick1;          // K1 ticket; finalize zeroes
__device__ unsigned int g_tick3;          // K3 ticket; finalize zeroes

// =====================================================================
// K1: per-cluster channel sums + counts via warp-private smem bins.
// 8 warps/block; warp owns 4 channels; lane owns a pixel quad.
// Software-pipelined: LDG burst for it+1 issues BEFORE scatter of it.
// Scatter uses float2 bins (LDS.64/STS.64, conflict-free).
// Walks x FORWARD (low->high addresses).
// Fused finalize: normalized means + inter hinge loss.
// =====================================================================
__global__ __launch_bounds__(256, 4) void k1_sums(const float* __restrict__ x,
                                                  const int* __restrict__ cmask)
{
    __shared__ unsigned char s_cm[PX1];
    __shared__ int s_cnt[KCL];
    __shared__ float2 s_acc2[8][KCL * 2 * 32];   // 8 warps x 640 float2 = 40 KB
    __shared__ unsigned int s_last;
    __shared__ float s_r[8];

    const int bid   = blockIdx.x;
    const int b     = bid / (CHUNKS1 * 2);
    const int r0    = bid % (CHUNKS1 * 2);
    const int cgrp  = r0 & 1;
    const int pbase = (r0 >> 1) * PX1;
    const int tid   = threadIdx.x;
    const int lane  = tid & 31;
    const int warp  = tid >> 5;

    if (tid < KCL) s_cnt[tid] = 0;

    // zero this warp's bins (warp-private: no cross-warp sync needed)
    float2* wacc2 = s_acc2[warp];
#pragma unroll
    for (int i = 0; i < (KCL * 2 * 32) / 32; i++)
        wacc2[i * 32 + lane] = make_float2(0.f, 0.f);

    // stage masks (+ counts only from channel-group 0)
    const int* cmb = cmask + b * KHW + pbase;
    if (cgrp == 0) {
        int cnt[KCL];
#pragma unroll
        for (int k = 0; k < KCL; k++) cnt[k] = 0;
#pragma unroll
        for (int i = 0; i < PX1 / 256; i++) {
            const int p = tid + i * 256;
            const int v = cmb[p];
            s_cm[p] = (unsigned char)v;
#pragma unroll
            for (int k = 0; k < KCL; k++) cnt[k] += (v == k);
        }
        __syncthreads();
#pragma unroll
        for (int k = 0; k < KCL; k++) {
            int v = cnt[k];
#pragma unroll
            for (int o = 16; o; o >>= 1) v += __shfl_xor_sync(0xffffffffu, v, o);
            if (lane == 0) atomicAdd(&s_cnt[k], v);
        }
        __syncthreads();
        if (tid < KCL) atomicAdd(&g_cnt[b][tid], (float)s_cnt[tid]);
    } else {
#pragma unroll
        for (int i = 0; i < PX1 / 256; i++) {
            const int p = tid + i * 256;
            s_cm[p] = (unsigned char)cmb[p];
        }
        __syncthreads();
    }

    // ---- main accumulation: software-pipelined quad loop ----
    const int c0 = cgrp * 32 + warp * 4;
    const float* xp = x + ((size_t)(b * KC + c0)) * KHW + pbase;

#define LOADQ(d0, d1, d2, d3, P)                                   \
    d0 = *(const float4*)(xp + (P));                               \
    d1 = *(const float4*)(xp + (size_t)KHW + (P));                 \
    d2 = *(const float4*)(xp + (size_t)2 * KHW + (P));             \
    d3 = *(const float4*)(xp + (size_t)3 * KHW + (P))

#define SCATTER_PX(KV, V0, V1, V2, V3) do {                        \
    float2* a = wacc2 + (KV) * 64 + lane;                          \
    float2 t0 = a[0];  t0.x += (V0); t0.y += (V1); a[0]  = t0;     \
    float2 t1 = a[32]; t1.x += (V2); t1.y += (V3); a[32] = t1;     \
} while (0)

    float4 c0v, c1v, c2v, c3v;
    unsigned int cmq;
    {
        const int p = 4 * lane;
        LOADQ(c0v, c1v, c2v, c3v, p);
        cmq = *(const unsigned int*)(s_cm + p);
    }

#pragma unroll
    for (int it = 0; it < PX1 / 128; it++) {
        float4 n0, n1, n2, n3;
        unsigned int cmn = 0;
        if (it + 1 < PX1 / 128) {
            const int pn = 4 * lane + (it + 1) * 128;
            LOADQ(n0, n1, n2, n3, pn);                 // burst for it+1
            cmn = *(const unsigned int*)(s_cm + pn);
        }

        // scatter current quad (overlaps with the burst above)
        SCATTER_PX(cmq & 0xffu,         c0v.x, c1v.x, c2v.x, c3v.x);
        SCATTER_PX((cmq >> 8) & 0xffu,  c0v.y, c1v.y, c2v.y, c3v.y);
        SCATTER_PX((cmq >> 16) & 0xffu, c0v.z, c1v.z, c2v.z, c3v.z);
        SCATTER_PX(cmq >> 24,           c0v.w, c1v.w, c2v.w, c3v.w);

        c0v = n0; c1v = n1; c2v = n2; c3v = n3; cmq = cmn;
    }
#undef LOADQ
#undef SCATTER_PX

    // ---- per-warp reduce of bins -> global atomics ----
#pragma unroll
    for (int r = 0; r < KCL * 2; r++) {
        float2 v = wacc2[r * 32 + lane];
#pragma unroll
        for (int o = 16; o; o >>= 1) {
            v.x += __shfl_xor_sync(0xffffffffu, v.x, o);
            v.y += __shfl_xor_sync(0xffffffffu, v.y, o);
        }
        if (lane == 0) {
            const int k  = r >> 1;
            const int jp = r & 1;
            atomicAdd(&g_sums[b][c0 + 2 * jp][k],     v.x);
            atomicAdd(&g_sums[b][c0 + 2 * jp + 1][k], v.y);
        }
    }

    // ---- ticket: last block computes means + inter loss ----
    __threadfence();
    __syncthreads();
    if (tid == 0)
        s_last = (atomicAdd(&g_tick1, 1u) == (unsigned)(NBLK1 - 1)) ? 1u : 0u;
    __syncthreads();
    if (!s_last) return;
    __threadfence();

    // bins are dead now; alias them as the means staging buffer (80x65 floats)
    float* s_means = (float*)&s_acc2[0][0];

    // means: 80 rows (b,k); warp per row stripe, lanes cover c and c+32
    for (int row = warp; row < KB * KCL; row += 8) {
        const int bb = row / KCL;
        const int kk = row % KCL;
        const float cntv = g_cnt[bb][kk];
        const float m0 = g_sums[bb][lane][kk]      / (cntv + 1e-10f);
        const float m1 = g_sums[bb][lane + 32][kk] / (cntv + 1e-10f);
        float sq = m0 * m0 + m1 * m1;
#pragma unroll
        for (int o = 16; o; o >>= 1) sq += __shfl_xor_sync(0xffffffffu, sq, o);
        const float inv = 1.0f / fmaxf(sqrtf(sq), 1e-12f);
        const float n0 = m0 * inv, n1 = m1 * inv;
        g_means[bb][kk][lane]      = n0;
        g_means[bb][kk][lane + 32] = n1;
        s_means[row * 65 + lane]      = n0;
        s_means[row * 65 + lane + 32] = n1;
        // reset for next launch
        g_sums[bb][lane][kk]      = 0.0f;
        g_sums[bb][lane + 32][kk] = 0.0f;
        if (lane == 0) g_cnt[bb][kk] = 0.0f;
    }
    __syncthreads();

    // inter loss: warp-per-ordered-pair (720 pairs / 8 warps), lane0 accum
    float acc_inter = 0.f;
    for (int pr = warp; pr < KB * KCL * (KCL - 1); pr += 8) {
        const int bb = pr / 90;
        const int r  = pr % 90;
        const int k  = r / 9;
        int l = r % 9; if (l >= k) l++;
        const float* mk = &s_means[(bb * KCL + k) * 65];
        const float* ml = &s_means[(bb * KCL + l) * 65];
        float dv = mk[lane] * ml[lane] + mk[lane + 32] * ml[lane + 32];
#pragma unroll
        for (int o = 16; o; o >>= 1) dv += __shfl_xor_sync(0xffffffffu, dv, o);
        const float h = fmaxf(DELTA_C - 0.5f * (1.0f - dv), 0.0f);
        if (lane == 0) acc_inter += h * h;
    }
    if (lane == 0) s_r[warp] = acc_inter;
    __syncthreads();
    if (tid == 0) {
        float t = 0.f;
#pragma unroll
        for (int w = 0; w < 8; w++) t += s_r[w];
        g_inter = t;
        g_tick1 = 0u;
    }
}

// =====================================================================
// K3: second pass, 4 px/thread, 8-wide channel windows with explicit
// 8x LDG.128 load burst. Walks x in REVERSE block order so its early
// blocks consume the x tail that K1 just left resident in L2 (and it
// leaves the x head resident for the next replay's K1) — L2 ping-pong.
// Ticket-last-block finalize: intra + combine with g_inter.
// =====================================================================
__global__ __launch_bounds__(128, 8) void k3_intra(const float* __restrict__ x,
                                                   const int* __restrict__ cmask,
                                                   float* __restrict__ out)
{
    __shared__ float msh[KCL * 65];
    __shared__ float s_d2[KCL];
    __shared__ float s_nk[KCL];
    __shared__ unsigned int s_last;

    const int rbid  = (NBLK3 - 1) - blockIdx.x;   // reversed traversal
    const int b     = rbid / CHUNKS3;
    const int pbase = (rbid % CHUNKS3) * PX3;
    const int tid   = threadIdx.x;
    const int lane  = tid & 31;
    const int warp  = tid >> 5;

#pragma unroll
    for (int i = 0; i < 5; i++) {
        const int idx = tid + i * 128;
        msh[(idx >> 6) * 65 + (idx & 63)] = ((const float*)g_means)[b * KCL * KC + idx];
    }
    if (tid < KCL) { s_d2[tid] = 0.f; s_nk[tid] = 0.f; }
    __syncthreads();

    const int p0 = pbase + tid * 4;
    const int4 cm4 = *(const int4*)(cmask + b * KHW + p0);
    const float* xb = x + (size_t)b * KC * KHW + p0;

    const int kk4[4] = { cm4.x, cm4.y, cm4.z, cm4.w };
    const float* mp0 = &msh[cm4.x * 65];
    const float* mp1 = &msh[cm4.y * 65];
    const float* mp2 = &msh[cm4.z * 65];
    const float* mp3 = &msh[cm4.w * 65];

    float d0 = 0.f, d1 = 0.f, d2 = 0.f, d3 = 0.f;

#pragma unroll
    for (int w = 0; w < KC / 8; w++) {
        // ---- load burst: 8 channels in flight ----
        float4 buf[8];
#pragma unroll
        for (int cc = 0; cc < 8; cc++)
            buf[cc] = *(const float4*)(xb + (size_t)(w * 8 + cc) * KHW);
        // ---- compute phase ----
#pragma unroll
        for (int cc = 0; cc < 8; cc++) {
            const int c = w * 8 + cc;
            d0 = fmaf(buf[cc].x, mp0[c], d0);
            d1 = fmaf(buf[cc].y, mp1[c], d1);
            d2 = fmaf(buf[cc].z, mp2[c], d2);
            d3 = fmaf(buf[cc].w, mp3[c], d3);
        }
    }

    const float dots[4] = { d0, d1, d2, d3 };
#pragma unroll
    for (int i = 0; i < 4; i++) {
        const float dd = 0.5f * (1.0f - dots[i]);
        atomicAdd(&s_d2[kk4[i]], dd * dd);
        if (dd > ALPHA_C) atomicAdd(&s_nk[kk4[i]], 1.0f);
    }
    __syncthreads();
    if (tid < KCL) {
        atomicAdd(&g_d2[b * KCL + tid], s_d2[tid]);
        atomicAdd(&g_nk[b * KCL + tid], s_nk[tid]);
    }

    // ---- ticket: last block finalizes ----
    __threadfence();
    __syncthreads();
    if (tid == 0)
        s_last = (atomicAdd(&g_tick3, 1u) == (unsigned)(NBLK3 - 1)) ? 1u : 0u;
    __syncthreads();
    if (!s_last) return;
    __threadfence();

    // intra finalize + resets (80 values)
    float acc_intra = 0.f, acc_ind = 0.f;
    if (tid < KB * KCL) {
        const float nk = g_nk[tid];
        acc_intra = g_d2[tid] / (fmaxf(nk, MINW_C) * (float)KCL);
        acc_ind   = nk;
        g_nk[tid] = 0.f;
        g_d2[tid] = 0.f;
    }

    float v1 = acc_intra, v2 = acc_ind;
#pragma unroll
    for (int o = 16; o; o >>= 1) {
        v1 += __shfl_xor_sync(0xffffffffu, v1, o);
        v2 += __shfl_xor_sync(0xffffffffu, v2, o);
    }
    __shared__ float s_r1[4], s_r2[4];
    if (lane == 0) { s_r1[warp] = v1; s_r2[warp] = v2; }
    __syncthreads();
    if (tid == 0) {
        float t1 = 0.f, t2 = 0.f;
#pragma unroll
        for (int w = 0; w < 4; w++) { t1 += s_r1[w]; t2 += s_r2[w]; }
        const float inter_loss = g_inter / ((float)(KCL * (KCL - 1) / 2) * (float)KB);
        const float intra_loss = (t2 > 0.f) ? (t1 / (float)KB) : 0.f;
        out[0] = intra_loss + inter_loss;
        out[1] = intra_loss;
        out[2] = inter_loss;
        g_tick3 = 0u;
    }
}

// =====================================================================
extern "C" void kernel_launch(void* const* d_in, const int* in_sizes, int n_in,
                              void* d_out, int out_size)
{
    const float* x   = (const float*)d_in[0];
    const int*   cm  = (const int*)d_in[1];
    float*       out = (float*)d_out;

    k1_sums<<<NBLK1, 256>>>(x, cm);
    k3_intra<<<NBLK3, 128>>>(x, cm, out);
}